// round 15
// baseline (speedup 1.0000x reference)
#include <cuda_runtime.h>
#include <cuda_fp16.h>
#include <math.h>
#include <stdint.h>

#define BB 4
#define TT 2048
#define DD 1024
#define HH 16
#define HD 64
#define MM (BB*TT)           // 8192
#define N3 (3*DD)            // 3072

// Scratch (device globals: allocation-guard-safe)
__device__ __half g_qh[BB*HH*TT*HD];   // [B,H,T,hd]
__device__ __half g_kh[BB*HH*TT*HD];
__device__ __half g_vh[BB*HH*TT*HD];
__device__ __half g_yh[MM*DD];         // [B,T,D]
__device__ __half g_wah[DD*N3];
__device__ __half g_wph[DD*DD];

__device__ __forceinline__ uint32_t saddr(const void* p) {
    return (uint32_t)__cvta_generic_to_shared(p);
}
__device__ __forceinline__ uint32_t packh2(float a, float b) {
    __half2 h = __floats2half2_rn(a, b);
    return *(uint32_t*)&h;
}

#define MMA_F16(d, a, b) \
    asm volatile("mma.sync.aligned.m16n8k16.row.col.f32.f16.f16.f32 " \
        "{%0,%1,%2,%3}, {%4,%5,%6,%7}, {%8,%9}, {%0,%1,%2,%3};" \
        : "+f"((d)[0]), "+f"((d)[1]), "+f"((d)[2]), "+f"((d)[3]) \
        : "r"((a)[0]), "r"((a)[1]), "r"((a)[2]), "r"((a)[3]), \
          "r"((b)[0]), "r"((b)[1]))

#define LDSM_X4(r0, r1, r2, r3, a) \
    asm volatile("ldmatrix.sync.aligned.m8n8.x4.shared.b16 {%0,%1,%2,%3}, [%4];" \
        : "=r"(r0), "=r"(r1), "=r"(r2), "=r"(r3) : "r"(a))

#define LDSM_X4_T(r0, r1, r2, r3, a) \
    asm volatile("ldmatrix.sync.aligned.m8n8.x4.trans.shared.b16 {%0,%1,%2,%3}, [%4];" \
        : "=r"(r0), "=r"(r1), "=r"(r2), "=r"(r3) : "r"(a))

// Attention-only async copy (.cg won R9; GEMM uses LDG+STS per R8/R10 data)
#define CP_ASYNC(dst, src) \
    asm volatile("cp.async.cg.shared.global [%0], [%1], 16;" :: "r"(dst), "l"(src))
#define CP_COMMIT() asm volatile("cp.async.commit_group;" ::: "memory")
#define CP_WAIT0()  asm volatile("cp.async.wait_group 0;" ::: "memory")

// ---------------------------------------------------------------------------
// Fused fp32 -> fp16 conversion: weights only (x converts inside QKV GEMM)
// ---------------------------------------------------------------------------
#define NA4 (DD * N3 / 4)
#define NP4 (DD * DD / 4)

__global__ __launch_bounds__(256)
void f2h_w(const float4* __restrict__ wa, __half2* __restrict__ wao,
           const float4* __restrict__ wp, __half2* __restrict__ wpo)
{
    const int total = NA4 + NP4;
    int i = blockIdx.x * blockDim.x + threadIdx.x;
    const int stride = gridDim.x * blockDim.x;
    for (; i < total; i += stride) {
        const float4* src;
        __half2* dst;
        int j;
        if (i < NA4) { src = wa; dst = wao; j = i; }
        else         { src = wp; dst = wpo; j = i - NA4; }
        float4 v = src[j];
        dst[2 * j + 0] = __floats2half2_rn(v.x, v.y);
        dst[2 * j + 1] = __floats2half2_rn(v.z, v.w);
    }
}

// ---------------------------------------------------------------------------
// fp16 tensor-core GEMM. CTA 128x128, 8 warps (2M x 4N), warp 64x32.
// MODE 0: A is fp32 (x), converted at STS; KSTAGE=16; scatter fp16 q/k/v.
// MODE 1: A is fp16 (yh); KSTAGE=32 (R8-proven path); fp32 C out.
// ---------------------------------------------------------------------------
template<int MODE, int NTOT>
__global__ __launch_bounds__(256, 2)
void mma_gemm(const void* __restrict__ Araw, const __half* __restrict__ B,
              const float* __restrict__ bias, float* __restrict__ C)
{
    __shared__ __half As[2][128][40];
    __shared__ __half Bs[2][32][136];

    const int tid = threadIdx.x;
    const int lane = tid & 31;
    const int wid = tid >> 5;
    const int warp_m = wid >> 2;
    const int warp_n = wid & 3;
    const int g = lane >> 2;
    const int tg = lane & 3;
    const int bx = blockIdx.x, by = blockIdx.y;

    const __half* Bg = B + bx * 128;

    const int lrow = (lane & 7) + ((lane >> 3) & 1) * 8;
    const int lch  = ((lane >> 4) & 1) * 8;
    const int trow = (lane & 7) + ((lane >> 3) & 1) * 8;
    const int tcn  = ((lane >> 4) & 1) * 8;

    float acc[4][4][4];
    #pragma unroll
    for (int i = 0; i < 4; i++)
        #pragma unroll
        for (int j = 0; j < 4; j++)
            #pragma unroll
            for (int r = 0; r < 4; r++) acc[i][j][r] = 0.0f;

    if (MODE == 0) {
        // ---- fp32-A path, KSTAGE=16 ----
        const float* Ag = (const float*)Araw + (size_t)(by * 128) * 1024;
        const int ar  = tid >> 1;            // 0..127
        const int akc = (tid & 1) << 3;      // 0,8
        const int br  = tid >> 4;            // 0..15
        const int bnc = (tid & 15) << 3;     // 0..120

        float4 fa0 = *(const float4*)&Ag[(size_t)ar * 1024 + akc];
        float4 fa1 = *(const float4*)&Ag[(size_t)ar * 1024 + akc + 4];
        uint4 rb   = *(const uint4*)&Bg[(size_t)br * NTOT + bnc];

        for (int s = 0; s < 64; s++) {
            const int buf = s & 1;
            uint4 ca;
            ca.x = packh2(fa0.x, fa0.y);
            ca.y = packh2(fa0.z, fa0.w);
            ca.z = packh2(fa1.x, fa1.y);
            ca.w = packh2(fa1.z, fa1.w);
            *(uint4*)&As[buf][ar][akc] = ca;
            *(uint4*)&Bs[buf][br][bnc] = rb;
            __syncthreads();

            if (s < 63) {
                const int kb = (s + 1) * 16;
                fa0 = *(const float4*)&Ag[(size_t)ar * 1024 + kb + akc];
                fa1 = *(const float4*)&Ag[(size_t)ar * 1024 + kb + akc + 4];
                rb  = *(const uint4*)&Bg[(size_t)(kb + br) * NTOT + bnc];
            }

            uint32_t af[4][4];
            #pragma unroll
            for (int mi = 0; mi < 4; mi++) {
                const uint32_t a = saddr(&As[buf][warp_m * 64 + mi * 16 + lrow][lch]);
                LDSM_X4(af[mi][0], af[mi][1], af[mi][2], af[mi][3], a);
            }
            uint32_t bf[4][2];
            #pragma unroll
            for (int nn = 0; nn < 2; nn++) {
                const uint32_t a = saddr(&Bs[buf][trow][warp_n * 32 + nn * 16 + tcn]);
                LDSM_X4_T(bf[2 * nn][0], bf[2 * nn][1], bf[2 * nn + 1][0], bf[2 * nn + 1][1], a);
            }
            #pragma unroll
            for (int mi = 0; mi < 4; mi++)
                #pragma unroll
                for (int ni = 0; ni < 4; ni++)
                    MMA_F16(acc[mi][ni], af[mi], bf[ni]);
        }
    } else {
        // ---- fp16-A path, KSTAGE=32 (R8-proven) ----
        const __half* Ag = (const __half*)Araw + (size_t)(by * 128) * 1024;
        const int ar  = tid >> 2;
        const int akc = (tid & 3) << 3;
        const int br  = tid >> 4;
        const int bnc = (tid & 15) << 3;

        uint4 ra0 = *(const uint4*)&Ag[(size_t)ar * 1024 + akc];
        uint4 ra1 = *(const uint4*)&Ag[(size_t)(ar + 64) * 1024 + akc];
        uint4 rb0 = *(const uint4*)&Bg[(size_t)br * NTOT + bnc];
        uint4 rb1 = *(const uint4*)&Bg[(size_t)(br + 16) * NTOT + bnc];

        for (int s = 0; s < 32; s++) {
            const int buf = s & 1;
            *(uint4*)&As[buf][ar][akc]       = ra0;
            *(uint4*)&As[buf][ar + 64][akc]  = ra1;
            *(uint4*)&Bs[buf][br][bnc]       = rb0;
            *(uint4*)&Bs[buf][br + 16][bnc]  = rb1;
            __syncthreads();

            if (s < 31) {
                const int kb = (s + 1) * 32;
                ra0 = *(const uint4*)&Ag[(size_t)ar * 1024 + kb + akc];
                ra1 = *(const uint4*)&Ag[(size_t)(ar + 64) * 1024 + kb + akc];
                rb0 = *(const uint4*)&Bg[(size_t)(kb + br) * NTOT + bnc];
                rb1 = *(const uint4*)&Bg[(size_t)(kb + br + 16) * NTOT + bnc];
            }

            #pragma unroll
            for (int ks = 0; ks < 2; ks++) {
                const int k16 = ks * 16;
                uint32_t af[4][4];
                #pragma unroll
                for (int mi = 0; mi < 4; mi++) {
                    const uint32_t a = saddr(&As[buf][warp_m * 64 + mi * 16 + lrow][k16 + lch]);
                    LDSM_X4(af[mi][0], af[mi][1], af[mi][2], af[mi][3], a);
                }
                uint32_t bf[4][2];
                #pragma unroll
                for (int nn = 0; nn < 2; nn++) {
                    const uint32_t a = saddr(&Bs[buf][k16 + trow][warp_n * 32 + nn * 16 + tcn]);
                    LDSM_X4_T(bf[2 * nn][0], bf[2 * nn][1], bf[2 * nn + 1][0], bf[2 * nn + 1][1], a);
                }
                #pragma unroll
                for (int mi = 0; mi < 4; mi++)
                    #pragma unroll
                    for (int ni = 0; ni < 4; ni++)
                        MMA_F16(acc[mi][ni], af[mi], bf[ni]);
            }
        }
    }

    #pragma unroll
    for (int mi = 0; mi < 4; mi++) {
        #pragma unroll
        for (int ni = 0; ni < 4; ni++) {
            const int n = bx * 128 + warp_n * 32 + ni * 8 + 2 * tg;
            const float b0 = bias[n], b1 = bias[n + 1];
            #pragma unroll
            for (int p = 0; p < 2; p++) {
                const int m = by * 128 + warp_m * 64 + mi * 16 + g + p * 8;
                const float vx = acc[mi][ni][2 * p + 0] + b0;
                const float vy = acc[mi][ni][2 * p + 1] + b1;
                if (MODE == 0) {
                    const int b_ = m >> 11;
                    const int t_ = m & 2047;
                    const int sel = n >> 10;
                    const int d = n & 1023;
                    __half* dst = (sel == 0) ? g_qh : ((sel == 1) ? g_kh : g_vh);
                    *(__half2*)&dst[((size_t)(b_ * 16 + (d >> 6)) * 2048 + t_) * 64 + (d & 63)] =
                        __floats2half2_rn(vx, vy);
                } else {
                    float2 v; v.x = vx; v.y = vy;
                    *(float2*)&C[(size_t)m * NTOT + n] = v;
                }
            }
        }
    }
}

// ---------------------------------------------------------------------------
// fp16 flash attention: cp.async.cg K/V double-buffer + register-resident P.
// LPT scheduling: heaviest q-tiles launch first.
// ---------------------------------------------------------------------------
#define PSTR 72
#define ATTN_SMEM ((4 * 64 * PSTR + 8 * 16 * PSTR) * 2)   // 55296 B

__global__ __launch_bounds__(256, 2)
void attn_tc()
{
    extern __shared__ __half hsm[];
    __half (*Ks)[64][PSTR] = (__half (*)[64][PSTR])hsm;
    __half (*Vs)[64][PSTR] = (__half (*)[64][PSTR])(hsm + 2 * 64 * PSTR);
    __half (*Ps)[16][PSTR] = (__half (*)[16][PSTR])(hsm + 4 * 64 * PSTR);  // Q stage only

    const int tid  = threadIdx.x;
    const int lane = tid & 31;
    const int wid  = tid >> 5;
    const int g    = lane >> 2;
    const int tg   = lane & 3;
    const int qt = gridDim.x - 1 - blockIdx.x;   // LPT: big CTAs first
    const int h  = blockIdx.y;
    const int b  = blockIdx.z;

    const __half* qb = g_qh + (size_t)(b * HH + h) * TT * HD;
    const __half* kb = g_kh + (size_t)(b * HH + h) * TT * HD;
    const __half* vb = g_vh + (size_t)(b * HH + h) * TT * HD;

    __half (*Pw)[PSTR] = Ps[wid];

    const int arow = (lane & 7) + ((lane >> 3) & 1) * 8;
    const int ach  = ((lane >> 4) & 1) * 8;
    const int krow = (lane & 7) + ((lane >> 4) & 1) * 8;
    const int kch  = ((lane >> 3) & 1) * 8;
    const int vrow = (lane & 7) + ((lane >> 3) & 1) * 8;
    const int vcn  = ((lane >> 4) & 1) * 8;

    const int sr = tid >> 2;             // 0..63
    const int sc = (tid & 3) << 3;       // 0,8,16,24 (chunks at sc, sc+32)

    auto issueKV = [&](int kt, int buf) {
        const __half* kr = kb + (size_t)(kt * 64 + sr) * 64;
        const __half* vr = vb + (size_t)(kt * 64 + sr) * 64;
        CP_ASYNC(saddr(&Ks[buf][sr][sc]),      kr + sc);
        CP_ASYNC(saddr(&Ks[buf][sr][sc + 32]), kr + sc + 32);
        CP_ASYNC(saddr(&Vs[buf][sr][sc]),      vr + sc);
        CP_ASYNC(saddr(&Vs[buf][sr][sc + 32]), vr + sc + 32);
        CP_COMMIT();
    };

    const int nkt = 2 * qt + 2;
    issueKV(0, 0);

    // ---- load Q fragments into registers (once) ----
    uint32_t Qf[4][4];
    {
        const int r = lane >> 1;
        const int c = (lane & 1) * 32;
        const __half* qrow = qb + (size_t)(qt * 128 + wid * 16 + r) * 64 + c;
        #pragma unroll
        for (int i = 0; i < 4; i++)
            *(uint4*)&Pw[r][c + i * 8] = *(const uint4*)&qrow[i * 8];
        __syncwarp();
        #pragma unroll
        for (int ks = 0; ks < 4; ks++) {
            const uint32_t a = saddr(&Pw[arow][ks * 16 + ach]);
            LDSM_X4(Qf[ks][0], Qf[ks][1], Qf[ks][2], Qf[ks][3], a);
        }
    }

    float O[8][4];
    #pragma unroll
    for (int ni = 0; ni < 8; ni++)
        #pragma unroll
        for (int r = 0; r < 4; r++) O[ni][r] = 0.0f;
    float mi0 = -INFINITY, mi1 = -INFINITY, li0 = 0.0f, li1 = 0.0f;

    const int row0 = qt * 128 + wid * 16 + g;
    const int row1 = row0 + 8;
    const int wrow_min = qt * 128 + wid * 16;
    const float scale = 0.125f;

    for (int kt = 0; kt < nkt; kt++) {
        CP_WAIT0();
        __syncthreads();
        if (kt + 1 < nkt) issueKV(kt + 1, (kt + 1) & 1);
        const int bk = kt & 1;

        // ---- S = Q K^T ----
        float S[8][4];
        #pragma unroll
        for (int ni = 0; ni < 8; ni++)
            #pragma unroll
            for (int r = 0; r < 4; r++) S[ni][r] = 0.0f;

        #pragma unroll
        for (int ks = 0; ks < 4; ks++) {
            uint32_t bf[8][2];
            #pragma unroll
            for (int np = 0; np < 4; np++) {
                const uint32_t a = saddr(&Ks[bk][np * 16 + krow][ks * 16 + kch]);
                LDSM_X4(bf[2 * np][0], bf[2 * np][1], bf[2 * np + 1][0], bf[2 * np + 1][1], a);
            }
            #pragma unroll
            for (int ni = 0; ni < 8; ni++)
                MMA_F16(S[ni], Qf[ks], bf[ni]);
        }

        if (kt * 64 + 63 > wrow_min) {
            #pragma unroll
            for (int ni = 0; ni < 8; ni++) {
                const int c0 = kt * 64 + ni * 8 + 2 * tg;
                S[ni][0] = (c0     > row0) ? -INFINITY : S[ni][0] * scale;
                S[ni][1] = (c0 + 1 > row0) ? -INFINITY : S[ni][1] * scale;
                S[ni][2] = (c0     > row1) ? -INFINITY : S[ni][2] * scale;
                S[ni][3] = (c0 + 1 > row1) ? -INFINITY : S[ni][3] * scale;
            }
        } else {
            #pragma unroll
            for (int ni = 0; ni < 8; ni++) {
                S[ni][0] *= scale; S[ni][1] *= scale;
                S[ni][2] *= scale; S[ni][3] *= scale;
            }
        }

        // ---- online softmax ----
        float m0 = -INFINITY, m1 = -INFINITY;
        #pragma unroll
        for (int ni = 0; ni < 8; ni++) {
            m0 = fmaxf(m0, fmaxf(S[ni][0], S[ni][1]));
            m1 = fmaxf(m1, fmaxf(S[ni][2], S[ni][3]));
        }
        m0 = fmaxf(m0, __shfl_xor_sync(0xffffffffu, m0, 1));
        m0 = fmaxf(m0, __shfl_xor_sync(0xffffffffu, m0, 2));
        m1 = fmaxf(m1, __shfl_xor_sync(0xffffffffu, m1, 1));
        m1 = fmaxf(m1, __shfl_xor_sync(0xffffffffu, m1, 2));
        const float mn0 = fmaxf(mi0, m0);
        const float mn1 = fmaxf(mi1, m1);
        const float a0 = __expf(mi0 - mn0);
        const float a1 = __expf(mi1 - mn1);
        mi0 = mn0; mi1 = mn1;

        // P packed directly into A-fragment registers
        uint32_t ph[8][2];
        float rs0 = 0.0f, rs1 = 0.0f;
        #pragma unroll
        for (int ni = 0; ni < 8; ni++) {
            const float p00 = __expf(S[ni][0] - mn0);
            const float p01 = __expf(S[ni][1] - mn0);
            const float p10 = __expf(S[ni][2] - mn1);
            const float p11 = __expf(S[ni][3] - mn1);
            rs0 += p00 + p01;
            rs1 += p10 + p11;
            ph[ni][0] = packh2(p00, p01);
            ph[ni][1] = packh2(p10, p11);
            O[ni][0] *= a0; O[ni][1] *= a0;
            O[ni][2] *= a1; O[ni][3] *= a1;
        }
        rs0 += __shfl_xor_sync(0xffffffffu, rs0, 1);
        rs0 += __shfl_xor_sync(0xffffffffu, rs0, 2);
        rs1 += __shfl_xor_sync(0xffffffffu, rs1, 1);
        rs1 += __shfl_xor_sync(0xffffffffu, rs1, 2);
        li0 = li0 * a0 + rs0;
        li1 = li1 * a1 + rs1;

        // ---- O += P V ----
        #pragma unroll
        for (int ks = 0; ks < 4; ks++) {
            uint32_t af[4];
            af[0] = ph[2 * ks][0];
            af[1] = ph[2 * ks][1];
            af[2] = ph[2 * ks + 1][0];
            af[3] = ph[2 * ks + 1][1];
            uint32_t bf[8][2];
            #pragma unroll
            for (int np = 0; np < 4; np++) {
                const uint32_t a = saddr(&Vs[bk][ks * 16 + vrow][np * 16 + vcn]);
                LDSM_X4_T(bf[2 * np][0], bf[2 * np][1], bf[2 * np + 1][0], bf[2 * np + 1][1], a);
            }
            #pragma unroll
            for (int ni = 0; ni < 8; ni++)
                MMA_F16(O[ni], af, bf[ni]);
        }
    }

    const float inv0 = 1.0f / li0;
    const float inv1 = 1.0f / li1;
    __half* y0 = g_yh + (size_t)(b * TT + row0) * DD + h * HD;
    __half* y1 = g_yh + (size_t)(b * TT + row1) * DD + h * HD;
    #pragma unroll
    for (int ni = 0; ni < 8; ni++) {
        const int c = ni * 8 + 2 * tg;
        *(__half2*)&y0[c] = __floats2half2_rn(O[ni][0] * inv0, O[ni][1] * inv0);
        *(__half2*)&y1[c] = __floats2half2_rn(O[ni][2] * inv1, O[ni][3] * inv1);
    }
}

// ---------------------------------------------------------------------------
extern "C" void kernel_launch(void* const* d_in, const int* in_sizes, int n_in,
                              void* d_out, int out_size)
{
    (void)in_sizes; (void)n_in; (void)out_size;
    const float* x      = (const float*)d_in[0];
    const float* W_attn = (const float*)d_in[1];
    const float* b_attn = (const float*)d_in[2];
    const float* W_proj = (const float*)d_in[3];
    const float* b_proj = (const float*)d_in[4];
    float* out = (float*)d_out;

    __half *wah = nullptr, *wph = nullptr, *yh = nullptr;
    cudaGetSymbolAddress((void**)&wah, g_wah);
    cudaGetSymbolAddress((void**)&wph, g_wph);
    cudaGetSymbolAddress((void**)&yh, g_yh);

    static bool attr_done = false;
    if (!attr_done) {
        cudaFuncSetAttribute(attn_tc, cudaFuncAttributeMaxDynamicSharedMemorySize, ATTN_SMEM);
        attr_done = true;
    }

    // 0) convert weights to fp16 (x converts inside the QKV GEMM)
    f2h_w<<<592, 256>>>((const float4*)W_attn, (__half2*)wah,
                        (const float4*)W_proj, (__half2*)wph);

    // 1) QKV projection from fp32 x (fused convert) + head-layout scatter
    mma_gemm<0, N3><<<dim3(N3 / 128, MM / 128), 256>>>(x, wah, b_attn, nullptr);

    // 2) causal flash attention (register-P, LPT-ordered)
    attn_tc<<<dim3(TT / 128, HH, BB), 256, ATTN_SMEM>>>();

    // 3) output projection (fp32 out)
    mma_gemm<1, DD><<<dim3(DD / 128, MM / 128), 256>>>(yh, wph, b_proj, out);
}

// round 16
// speedup vs baseline: 1.1576x; 1.1576x over previous
#include <cuda_runtime.h>
#include <cuda_fp16.h>
#include <math.h>
#include <stdint.h>

#define BB 4
#define TT 2048
#define DD 1024
#define HH 16
#define HD 64
#define MM (BB*TT)           // 8192
#define N3 (3*DD)            // 3072

// Scratch (device globals: allocation-guard-safe)
__device__ __half g_qh[BB*HH*TT*HD];   // [B,H,T,hd]
__device__ __half g_kh[BB*HH*TT*HD];
__device__ __half g_vh[BB*HH*TT*HD];
__device__ __half g_yh[MM*DD];         // [B,T,D]
__device__ __half g_xh[MM*DD];
__device__ __half g_wah[DD*N3];
__device__ __half g_wph[DD*DD];

__device__ __forceinline__ uint32_t saddr(const void* p) {
    return (uint32_t)__cvta_generic_to_shared(p);
}
__device__ __forceinline__ uint32_t packh2(float a, float b) {
    __half2 h = __floats2half2_rn(a, b);
    return *(uint32_t*)&h;
}

#define MMA_F16(d, a, b) \
    asm volatile("mma.sync.aligned.m16n8k16.row.col.f32.f16.f16.f32 " \
        "{%0,%1,%2,%3}, {%4,%5,%6,%7}, {%8,%9}, {%0,%1,%2,%3};" \
        : "+f"((d)[0]), "+f"((d)[1]), "+f"((d)[2]), "+f"((d)[3]) \
        : "r"((a)[0]), "r"((a)[1]), "r"((a)[2]), "r"((a)[3]), \
          "r"((b)[0]), "r"((b)[1]))

#define LDSM_X4(r0, r1, r2, r3, a) \
    asm volatile("ldmatrix.sync.aligned.m8n8.x4.shared.b16 {%0,%1,%2,%3}, [%4];" \
        : "=r"(r0), "=r"(r1), "=r"(r2), "=r"(r3) : "r"(a))

#define LDSM_X4_T(r0, r1, r2, r3, a) \
    asm volatile("ldmatrix.sync.aligned.m8n8.x4.trans.shared.b16 {%0,%1,%2,%3}, [%4];" \
        : "=r"(r0), "=r"(r1), "=r"(r2), "=r"(r3) : "r"(a))

// Attention-only async copy (.cg won R9; GEMM uses LDG+STS per R8/R10/R15 data)
#define CP_ASYNC(dst, src) \
    asm volatile("cp.async.cg.shared.global [%0], [%1], 16;" :: "r"(dst), "l"(src))
#define CP_COMMIT() asm volatile("cp.async.commit_group;" ::: "memory")
#define CP_WAIT0()  asm volatile("cp.async.wait_group 0;" ::: "memory")

// ---------------------------------------------------------------------------
// Fused fp32 -> fp16 conversion of x, W_attn, W_proj in ONE launch
// ---------------------------------------------------------------------------
#define NX4 (MM * DD / 4)
#define NA4 (DD * N3 / 4)
#define NP4 (DD * DD / 4)

__global__ __launch_bounds__(256)
void f2h_all(const float4* __restrict__ x, __half2* __restrict__ xo,
             const float4* __restrict__ wa, __half2* __restrict__ wao,
             const float4* __restrict__ wp, __half2* __restrict__ wpo)
{
    const int total = NX4 + NA4 + NP4;
    int i = blockIdx.x * blockDim.x + threadIdx.x;
    const int stride = gridDim.x * blockDim.x;
    for (; i < total; i += stride) {
        const float4* src;
        __half2* dst;
        int j;
        if (i < NX4)            { src = x;  dst = xo;  j = i; }
        else if (i < NX4 + NA4) { src = wa; dst = wao; j = i - NX4; }
        else                    { src = wp; dst = wpo; j = i - NX4 - NA4; }
        float4 v = src[j];
        dst[2 * j + 0] = __floats2half2_rn(v.x, v.y);
        dst[2 * j + 1] = __floats2half2_rn(v.z, v.w);
    }
}

// ---------------------------------------------------------------------------
// fp16 tensor-core GEMM (R8-proven): LDG+STS double buffer, KSTAGE=32.
// CTA 128x128, 8 warps (2M x 4N), warp 64x32.
// ---------------------------------------------------------------------------
template<int MODE, int NTOT>
__global__ __launch_bounds__(256, 2)
void mma_gemm(const __half* __restrict__ A, const __half* __restrict__ B,
              const float* __restrict__ bias, float* __restrict__ C)
{
    __shared__ __half As[2][128][40];
    __shared__ __half Bs[2][32][136];

    const int tid = threadIdx.x;
    const int lane = tid & 31;
    const int wid = tid >> 5;
    const int warp_m = wid >> 2;
    const int warp_n = wid & 3;
    const int g = lane >> 2;
    const int tg = lane & 3;
    const int bx = blockIdx.x, by = blockIdx.y;

    const __half* Ag = A + (size_t)(by * 128) * 1024;
    const __half* Bg = B + bx * 128;

    const int ar  = tid >> 2;
    const int akc = (tid & 3) << 3;
    const int br  = tid >> 4;
    const int bnc = (tid & 15) << 3;

    const int lrow = (lane & 7) + ((lane >> 3) & 1) * 8;
    const int lch  = ((lane >> 4) & 1) * 8;
    const int trow = (lane & 7) + ((lane >> 3) & 1) * 8;
    const int tcn  = ((lane >> 4) & 1) * 8;

    float acc[4][4][4];
    #pragma unroll
    for (int i = 0; i < 4; i++)
        #pragma unroll
        for (int j = 0; j < 4; j++)
            #pragma unroll
            for (int r = 0; r < 4; r++) acc[i][j][r] = 0.0f;

    uint4 ra0 = *(const uint4*)&Ag[(size_t)ar * 1024 + akc];
    uint4 ra1 = *(const uint4*)&Ag[(size_t)(ar + 64) * 1024 + akc];
    uint4 rb0 = *(const uint4*)&Bg[(size_t)br * NTOT + bnc];
    uint4 rb1 = *(const uint4*)&Bg[(size_t)(br + 16) * NTOT + bnc];

    for (int s = 0; s < 32; s++) {
        const int buf = s & 1;

        *(uint4*)&As[buf][ar][akc]       = ra0;
        *(uint4*)&As[buf][ar + 64][akc]  = ra1;
        *(uint4*)&Bs[buf][br][bnc]       = rb0;
        *(uint4*)&Bs[buf][br + 16][bnc]  = rb1;
        __syncthreads();

        if (s < 31) {
            const int kb = (s + 1) * 32;
            ra0 = *(const uint4*)&Ag[(size_t)ar * 1024 + kb + akc];
            ra1 = *(const uint4*)&Ag[(size_t)(ar + 64) * 1024 + kb + akc];
            rb0 = *(const uint4*)&Bg[(size_t)(kb + br) * NTOT + bnc];
            rb1 = *(const uint4*)&Bg[(size_t)(kb + br + 16) * NTOT + bnc];
        }

        #pragma unroll
        for (int ks = 0; ks < 2; ks++) {
            const int k16 = ks * 16;
            uint32_t af[4][4];
            #pragma unroll
            for (int mi = 0; mi < 4; mi++) {
                const uint32_t a = saddr(&As[buf][warp_m * 64 + mi * 16 + lrow][k16 + lch]);
                LDSM_X4(af[mi][0], af[mi][1], af[mi][2], af[mi][3], a);
            }
            uint32_t bf[4][2];
            #pragma unroll
            for (int nn = 0; nn < 2; nn++) {
                const uint32_t a = saddr(&Bs[buf][k16 + trow][warp_n * 32 + nn * 16 + tcn]);
                LDSM_X4_T(bf[2 * nn][0], bf[2 * nn][1], bf[2 * nn + 1][0], bf[2 * nn + 1][1], a);
            }
            #pragma unroll
            for (int mi = 0; mi < 4; mi++)
                #pragma unroll
                for (int ni = 0; ni < 4; ni++)
                    MMA_F16(acc[mi][ni], af[mi], bf[ni]);
        }
    }

    #pragma unroll
    for (int mi = 0; mi < 4; mi++) {
        #pragma unroll
        for (int ni = 0; ni < 4; ni++) {
            const int n = bx * 128 + warp_n * 32 + ni * 8 + 2 * tg;
            const float b0 = bias[n], b1 = bias[n + 1];
            #pragma unroll
            for (int p = 0; p < 2; p++) {
                const int m = by * 128 + warp_m * 64 + mi * 16 + g + p * 8;
                const float vx = acc[mi][ni][2 * p + 0] + b0;
                const float vy = acc[mi][ni][2 * p + 1] + b1;
                if (MODE == 0) {
                    const int b_ = m >> 11;
                    const int t_ = m & 2047;
                    const int sel = n >> 10;
                    const int d = n & 1023;
                    __half* dst = (sel == 0) ? g_qh : ((sel == 1) ? g_kh : g_vh);
                    *(__half2*)&dst[((size_t)(b_ * 16 + (d >> 6)) * 2048 + t_) * 64 + (d & 63)] =
                        __floats2half2_rn(vx, vy);
                } else {
                    float2 v; v.x = vx; v.y = vy;
                    *(float2*)&C[(size_t)m * NTOT + n] = v;
                }
            }
        }
    }
}

// ---------------------------------------------------------------------------
// fp16 flash attention: cp.async.cg K/V double-buffer + register-resident P.
// LPT scheduling: heaviest q-tiles launch first (qt reversed vs blockIdx.x).
// ---------------------------------------------------------------------------
#define PSTR 72
#define ATTN_SMEM ((4 * 64 * PSTR + 8 * 16 * PSTR) * 2)   // 55296 B

__global__ __launch_bounds__(256, 2)
void attn_tc()
{
    extern __shared__ __half hsm[];
    __half (*Ks)[64][PSTR] = (__half (*)[64][PSTR])hsm;
    __half (*Vs)[64][PSTR] = (__half (*)[64][PSTR])(hsm + 2 * 64 * PSTR);
    __half (*Ps)[16][PSTR] = (__half (*)[16][PSTR])(hsm + 4 * 64 * PSTR);  // Q stage only

    const int tid  = threadIdx.x;
    const int lane = tid & 31;
    const int wid  = tid >> 5;
    const int g    = lane >> 2;
    const int tg   = lane & 3;
    const int qt = gridDim.x - 1 - blockIdx.x;   // LPT: big CTAs first
    const int h  = blockIdx.y;
    const int b  = blockIdx.z;

    const __half* qb = g_qh + (size_t)(b * HH + h) * TT * HD;
    const __half* kb = g_kh + (size_t)(b * HH + h) * TT * HD;
    const __half* vb = g_vh + (size_t)(b * HH + h) * TT * HD;

    __half (*Pw)[PSTR] = Ps[wid];

    const int arow = (lane & 7) + ((lane >> 3) & 1) * 8;
    const int ach  = ((lane >> 4) & 1) * 8;
    const int krow = (lane & 7) + ((lane >> 4) & 1) * 8;
    const int kch  = ((lane >> 3) & 1) * 8;
    const int vrow = (lane & 7) + ((lane >> 3) & 1) * 8;
    const int vcn  = ((lane >> 4) & 1) * 8;

    const int sr = tid >> 2;             // 0..63
    const int sc = (tid & 3) << 3;       // 0,8,16,24 (chunks at sc, sc+32)

    auto issueKV = [&](int kt, int buf) {
        const __half* kr = kb + (size_t)(kt * 64 + sr) * 64;
        const __half* vr = vb + (size_t)(kt * 64 + sr) * 64;
        CP_ASYNC(saddr(&Ks[buf][sr][sc]),      kr + sc);
        CP_ASYNC(saddr(&Ks[buf][sr][sc + 32]), kr + sc + 32);
        CP_ASYNC(saddr(&Vs[buf][sr][sc]),      vr + sc);
        CP_ASYNC(saddr(&Vs[buf][sr][sc + 32]), vr + sc + 32);
        CP_COMMIT();
    };

    const int nkt = 2 * qt + 2;
    issueKV(0, 0);

    // ---- load Q fragments into registers (once) ----
    uint32_t Qf[4][4];
    {
        const int r = lane >> 1;
        const int c = (lane & 1) * 32;
        const __half* qrow = qb + (size_t)(qt * 128 + wid * 16 + r) * 64 + c;
        #pragma unroll
        for (int i = 0; i < 4; i++)
            *(uint4*)&Pw[r][c + i * 8] = *(const uint4*)&qrow[i * 8];
        __syncwarp();
        #pragma unroll
        for (int ks = 0; ks < 4; ks++) {
            const uint32_t a = saddr(&Pw[arow][ks * 16 + ach]);
            LDSM_X4(Qf[ks][0], Qf[ks][1], Qf[ks][2], Qf[ks][3], a);
        }
    }

    float O[8][4];
    #pragma unroll
    for (int ni = 0; ni < 8; ni++)
        #pragma unroll
        for (int r = 0; r < 4; r++) O[ni][r] = 0.0f;
    float mi0 = -INFINITY, mi1 = -INFINITY, li0 = 0.0f, li1 = 0.0f;

    const int row0 = qt * 128 + wid * 16 + g;
    const int row1 = row0 + 8;
    const int wrow_min = qt * 128 + wid * 16;
    const float scale = 0.125f;

    for (int kt = 0; kt < nkt; kt++) {
        CP_WAIT0();
        __syncthreads();
        if (kt + 1 < nkt) issueKV(kt + 1, (kt + 1) & 1);
        const int bk = kt & 1;

        // ---- S = Q K^T ----
        float S[8][4];
        #pragma unroll
        for (int ni = 0; ni < 8; ni++)
            #pragma unroll
            for (int r = 0; r < 4; r++) S[ni][r] = 0.0f;

        #pragma unroll
        for (int ks = 0; ks < 4; ks++) {
            uint32_t bf[8][2];
            #pragma unroll
            for (int np = 0; np < 4; np++) {
                const uint32_t a = saddr(&Ks[bk][np * 16 + krow][ks * 16 + kch]);
                LDSM_X4(bf[2 * np][0], bf[2 * np][1], bf[2 * np + 1][0], bf[2 * np + 1][1], a);
            }
            #pragma unroll
            for (int ni = 0; ni < 8; ni++)
                MMA_F16(S[ni], Qf[ks], bf[ni]);
        }

        if (kt * 64 + 63 > wrow_min) {
            #pragma unroll
            for (int ni = 0; ni < 8; ni++) {
                const int c0 = kt * 64 + ni * 8 + 2 * tg;
                S[ni][0] = (c0     > row0) ? -INFINITY : S[ni][0] * scale;
                S[ni][1] = (c0 + 1 > row0) ? -INFINITY : S[ni][1] * scale;
                S[ni][2] = (c0     > row1) ? -INFINITY : S[ni][2] * scale;
                S[ni][3] = (c0 + 1 > row1) ? -INFINITY : S[ni][3] * scale;
            }
        } else {
            #pragma unroll
            for (int ni = 0; ni < 8; ni++) {
                S[ni][0] *= scale; S[ni][1] *= scale;
                S[ni][2] *= scale; S[ni][3] *= scale;
            }
        }

        // ---- online softmax ----
        float m0 = -INFINITY, m1 = -INFINITY;
        #pragma unroll
        for (int ni = 0; ni < 8; ni++) {
            m0 = fmaxf(m0, fmaxf(S[ni][0], S[ni][1]));
            m1 = fmaxf(m1, fmaxf(S[ni][2], S[ni][3]));
        }
        m0 = fmaxf(m0, __shfl_xor_sync(0xffffffffu, m0, 1));
        m0 = fmaxf(m0, __shfl_xor_sync(0xffffffffu, m0, 2));
        m1 = fmaxf(m1, __shfl_xor_sync(0xffffffffu, m1, 1));
        m1 = fmaxf(m1, __shfl_xor_sync(0xffffffffu, m1, 2));
        const float mn0 = fmaxf(mi0, m0);
        const float mn1 = fmaxf(mi1, m1);
        const float a0 = __expf(mi0 - mn0);
        const float a1 = __expf(mi1 - mn1);
        mi0 = mn0; mi1 = mn1;

        // P packed directly into A-fragment registers
        uint32_t ph[8][2];
        float rs0 = 0.0f, rs1 = 0.0f;
        #pragma unroll
        for (int ni = 0; ni < 8; ni++) {
            const float p00 = __expf(S[ni][0] - mn0);
            const float p01 = __expf(S[ni][1] - mn0);
            const float p10 = __expf(S[ni][2] - mn1);
            const float p11 = __expf(S[ni][3] - mn1);
            rs0 += p00 + p01;
            rs1 += p10 + p11;
            ph[ni][0] = packh2(p00, p01);
            ph[ni][1] = packh2(p10, p11);
            O[ni][0] *= a0; O[ni][1] *= a0;
            O[ni][2] *= a1; O[ni][3] *= a1;
        }
        rs0 += __shfl_xor_sync(0xffffffffu, rs0, 1);
        rs0 += __shfl_xor_sync(0xffffffffu, rs0, 2);
        rs1 += __shfl_xor_sync(0xffffffffu, rs1, 1);
        rs1 += __shfl_xor_sync(0xffffffffu, rs1, 2);
        li0 = li0 * a0 + rs0;
        li1 = li1 * a1 + rs1;

        // ---- O += P V ----
        #pragma unroll
        for (int ks = 0; ks < 4; ks++) {
            uint32_t af[4];
            af[0] = ph[2 * ks][0];
            af[1] = ph[2 * ks][1];
            af[2] = ph[2 * ks + 1][0];
            af[3] = ph[2 * ks + 1][1];
            uint32_t bf[8][2];
            #pragma unroll
            for (int np = 0; np < 4; np++) {
                const uint32_t a = saddr(&Vs[bk][ks * 16 + vrow][np * 16 + vcn]);
                LDSM_X4_T(bf[2 * np][0], bf[2 * np][1], bf[2 * np + 1][0], bf[2 * np + 1][1], a);
            }
            #pragma unroll
            for (int ni = 0; ni < 8; ni++)
                MMA_F16(O[ni], af, bf[ni]);
        }
    }

    const float inv0 = 1.0f / li0;
    const float inv1 = 1.0f / li1;
    __half* y0 = g_yh + (size_t)(b * TT + row0) * DD + h * HD;
    __half* y1 = g_yh + (size_t)(b * TT + row1) * DD + h * HD;
    #pragma unroll
    for (int ni = 0; ni < 8; ni++) {
        const int c = ni * 8 + 2 * tg;
        *(__half2*)&y0[c] = __floats2half2_rn(O[ni][0] * inv0, O[ni][1] * inv0);
        *(__half2*)&y1[c] = __floats2half2_rn(O[ni][2] * inv1, O[ni][3] * inv1);
    }
}

// ---------------------------------------------------------------------------
extern "C" void kernel_launch(void* const* d_in, const int* in_sizes, int n_in,
                              void* d_out, int out_size)
{
    (void)in_sizes; (void)n_in; (void)out_size;
    const float* x      = (const float*)d_in[0];
    const float* W_attn = (const float*)d_in[1];
    const float* b_attn = (const float*)d_in[2];
    const float* W_proj = (const float*)d_in[3];
    const float* b_proj = (const float*)d_in[4];
    float* out = (float*)d_out;

    __half *xh = nullptr, *wah = nullptr, *wph = nullptr, *yh = nullptr;
    cudaGetSymbolAddress((void**)&xh, g_xh);
    cudaGetSymbolAddress((void**)&wah, g_wah);
    cudaGetSymbolAddress((void**)&wph, g_wph);
    cudaGetSymbolAddress((void**)&yh, g_yh);

    static bool attr_done = false;
    if (!attr_done) {
        cudaFuncSetAttribute(attn_tc, cudaFuncAttributeMaxDynamicSharedMemorySize, ATTN_SMEM);
        attr_done = true;
    }

    // 0) convert x, W_attn, W_proj to fp16 in one fused launch
    f2h_all<<<1184, 256>>>((const float4*)x, (__half2*)xh,
                           (const float4*)W_attn, (__half2*)wah,
                           (const float4*)W_proj, (__half2*)wph);

    // 1) QKV projection + head-layout scatter (fp16 out)
    mma_gemm<0, N3><<<dim3(N3 / 128, MM / 128), 256>>>(xh, wah, b_attn, nullptr);

    // 2) causal flash attention (register-P, LPT-ordered)
    attn_tc<<<dim3(TT / 128, HH, BB), 256, ATTN_SMEM>>>();

    // 3) output projection (fp32 out)
    mma_gemm<1, DD><<<dim3(DD / 128, MM / 128), 256>>>(yh, wph, b_proj, out);
}